// round 7
// baseline (speedup 1.0000x reference)
#include <cuda_runtime.h>
#include <cstdint>
#include <cstddef>

typedef unsigned long long ull;

#define TS 2048
#define Y1_ELEMS ((size_t)TS * 64 * 256)

// scratch (allocation-free rule)
__device__ float g_gx[(size_t)TS * 64 * 1024];
__device__ float g_y0[(size_t)TS * 64 * 256];

__device__ __forceinline__ ull fma2(ull a, ull b, ull c) {
    ull d; asm("fma.rn.f32x2 %0,%1,%2,%3;" : "=l"(d) : "l"(a), "l"(b), "l"(c)); return d;
}
__device__ __forceinline__ ull mul2(ull a, ull b) {
    ull d; asm("mul.rn.f32x2 %0,%1,%2;" : "=l"(d) : "l"(a), "l"(b)); return d;
}
__device__ __forceinline__ ull add2(ull a, ull b) {
    ull d; asm("add.rn.f32x2 %0,%1,%2;" : "=l"(d) : "l"(a), "l"(b)); return d;
}
__device__ __forceinline__ ull pk(float lo, float hi) {
    ull r; asm("mov.b64 %0,{%1,%2};" : "=l"(r) : "f"(lo), "f"(hi)); return r;
}
__device__ __forceinline__ void upk(ull a, float& x, float& y) {
    asm("mov.b64 {%0,%1},%2;" : "=f"(x), "=f"(y) : "l"(a));
}
__device__ __forceinline__ ull dup2(float x) {
    ull r; asm("mov.b64 %0,{%1,%1};" : "=l"(r) : "f"(x)); return r;
}
__device__ __forceinline__ float ex2f(float x) {
    float r; asm("ex2.approx.f32 %0,%1;" : "=f"(r) : "f"(x)); return r;
}
__device__ __forceinline__ float rcpf(float x) {
    float r; asm("rcp.approx.f32 %0,%1;" : "=f"(r) : "f"(x)); return r;
}
__device__ __forceinline__ float sigf(float x) {
    return rcpf(1.f + ex2f(-1.44269504f * x));
}
__device__ __forceinline__ float tanhap(float x) {
    float r; asm("tanh.approx.f32 %0,%1;" : "=f"(r) : "f"(x)); return r;
}

// spin until cluster-published flag >= target (acquire orders later h reads)
__device__ __forceinline__ void fwait(unsigned addr, unsigned target) {
    unsigned v;
#pragma unroll 1
    do {
        asm volatile("ld.acquire.cluster.shared::cta.u32 %0, [%1];"
                     : "=r"(v) : "r"(addr) : "memory");
    } while ((int)(v - target) < 0);
}

// ---------------------------------------------------------------------------
// GEMM: g_gx[m][n] = A_row(m) . W[:,n] + bias[n],  M = TS*64, N = 1024
// mode 0: A_row(m) = x + ((m&63)*TS + (m>>6))*128, K=128
// mode 1: A_row(m) = g_y0 + m*256,                 K=256
// ---------------------------------------------------------------------------
__global__ void __launch_bounds__(256, 1)
gemm_k(const float* __restrict__ A, const float* __restrict__ W,
       const float* __restrict__ bias, int K, int mode)
{
    __shared__ float As[16][132];
    __shared__ float Bs[16][128];

    const int tid = threadIdx.x;
    const int n0 = blockIdx.x * 128;
    const int m0 = blockIdx.y * 128;

    const int ar = tid >> 1;
    const int ac = (tid & 1) * 8;
    const int m = m0 + ar;
    const float* arow = mode ? (g_y0 + (size_t)m * 256)
                             : (A + ((size_t)(m & 63) * TS + (m >> 6)) * 128);
    const float* wp = W + (size_t)(tid >> 4) * 1024 + n0 + (tid & 15) * 8;

    const int tm = tid >> 4, tn = tid & 15;

    ull acc[8][4];
#pragma unroll
    for (int i = 0; i < 8; ++i)
#pragma unroll
        for (int j = 0; j < 4; ++j) acc[i][j] = 0ull;

#pragma unroll 1
    for (int k0 = 0; k0 < K; k0 += 16) {
        float4 a0 = *(const float4*)(arow + k0 + ac);
        float4 a1 = *(const float4*)(arow + k0 + ac + 4);
        float4 w0 = *(const float4*)(wp + (size_t)k0 * 1024);
        float4 w1 = *(const float4*)(wp + (size_t)k0 * 1024 + 4);
        __syncthreads();
        As[ac + 0][ar] = a0.x; As[ac + 1][ar] = a0.y;
        As[ac + 2][ar] = a0.z; As[ac + 3][ar] = a0.w;
        As[ac + 4][ar] = a1.x; As[ac + 5][ar] = a1.y;
        As[ac + 6][ar] = a1.z; As[ac + 7][ar] = a1.w;
        *(float4*)&Bs[tid >> 4][(tid & 15) * 8] = w0;
        *(float4*)&Bs[tid >> 4][(tid & 15) * 8 + 4] = w1;
        __syncthreads();
#pragma unroll
        for (int kk = 0; kk < 16; ++kk) {
            float4 av0 = *(const float4*)&As[kk][tm * 8];
            float4 av1 = *(const float4*)&As[kk][tm * 8 + 4];
            float av[8] = {av0.x, av0.y, av0.z, av0.w, av1.x, av1.y, av1.z, av1.w};
            const ull* bp = (const ull*)&Bs[kk][0];
            ull bv[4];
#pragma unroll
            for (int c = 0; c < 4; ++c) bv[c] = bp[tn * 4 + c];
#pragma unroll
            for (int r = 0; r < 8; ++r) {
                ull a2 = dup2(av[r]);
#pragma unroll
                for (int c = 0; c < 4; ++c) acc[r][c] = fma2(a2, bv[c], acc[r][c]);
            }
        }
    }

    float bb[8];
#pragma unroll
    for (int c = 0; c < 8; ++c) bb[c] = bias[n0 + tn * 8 + c];

#pragma unroll
    for (int r = 0; r < 8; ++r) {
        float v[8];
#pragma unroll
        for (int c = 0; c < 4; ++c) upk(acc[r][c], v[2 * c], v[2 * c + 1]);
#pragma unroll
        for (int c = 0; c < 8; ++c) v[c] += bb[c];
        float* op = g_gx + (size_t)(m0 + tm * 8 + r) * 1024 + n0 + tn * 8;
        *(float4*)op = make_float4(v[0], v[1], v[2], v[3]);
        *(float4*)(op + 4) = make_float4(v[4], v[5], v[6], v[7]);
    }
}

// ---------------------------------------------------------------------------
// Recurrence: 16 clusters x 8 CTAs, 4 batch elems per cluster.
// CTA rank r owns hidden units [r*32, r*32+32). Warp w owns units
// jw = r*32 + w*4 + u (u=0..3), all gates/batches/k — warp self-contained.
// Matvec is ordered BY SOURCE RANK: iteration i consumes h of rank (r+i)&7,
// gated by that rank's monotonic flag (st.release.cluster / ld.acquire spin).
// Own rank (i=0) needs only the local bar.sync -> cross-CTA latency overlaps
// with the fma stream instead of preceding it.
// h layout [buf][k][batch] -> 1 LDS.128 per rank per lane.
// Reduce = 5-round reduce-scatter butterfly; lane l ends with (cp=l>>2,b=l&3).
// ---------------------------------------------------------------------------
__global__ void __launch_bounds__(256, 1) __cluster_dims__(8, 1, 1)
recur_k(const float* __restrict__ whh, float* __restrict__ out, int layer)
{
    __shared__ float hbuf[2][256][4];          // [buf][k][batch]
    __shared__ __align__(16) unsigned flags[8];

    const int tid  = threadIdx.x;
    const int w    = tid >> 5;
    const int lane = tid & 31;
    unsigned r;
    asm("mov.u32 %0, %%cluster_ctarank;" : "=r"(r));
    const int gb0 = (blockIdx.x >> 3) * 4;

    // epilogue identity
    const int cp = lane >> 2;          // col-pair 0..7
    const int b  = lane & 3;           // batch 0..3
    const int gp = cp & 1;             // 0 -> (f,i), 1 -> (o,g)
    const int u  = cp >> 1;
    const int jj = (int)r * 32 + w * 4 + u;
    const int colA = (2 * gp) * 256 + jj;

    // weights: wreg[i][cp] covers k = ((r+i)&7)*32 + lane, cols (cA, cA+256)
    ull wreg[8][8];
#pragma unroll
    for (int i = 0; i < 8; ++i) {
        const int rr = ((int)r + i) & 7;
        const int k = rr * 32 + lane;
#pragma unroll
        for (int cpi = 0; cpi < 8; ++cpi) {
            const int cA = (2 * (cpi & 1)) * 256 + (int)r * 32 + w * 4 + (cpi >> 1);
            const float* wp = whh + (size_t)k * 1024 + cA;
            wreg[i][cpi] = pk(wp[0], wp[256]);
        }
    }

    unsigned hb_loc  = (unsigned)__cvta_generic_to_shared(&hbuf[0][0][0]);
    unsigned fl_loc  = (unsigned)__cvta_generic_to_shared(&flags[0]);
    unsigned fpub = 0;
    if (tid < 8)
        asm("mapa.shared::cluster.u32 %0, %1, %2;"
            : "=r"(fpub) : "r"(fl_loc + r * 4u), "r"(tid));

    if (tid < 8) flags[tid] = 0u;
    for (int i = tid; i < 2 * 256 * 4; i += 256)
        ((float*)hbuf)[i] = 0.f;
    __syncthreads();
    asm volatile("barrier.cluster.arrive.aligned;" ::: "memory");
    asm volatile("barrier.cluster.wait.aligned;" ::: "memory");

    float cst = 0.f;
    float* yout = layer ? out : g_y0;
    float* hn = out + Y1_ELEMS + (size_t)layer * 16384;
    float* cn = out + Y1_ELEMS + 32768 + (size_t)layer * 16384;

    // byte offset of this lane's h slot (buffer 0); buffer 1 = +4096
    const unsigned hoff_b0 = hb_loc + (unsigned)((jj * 4 + b) * 4);

    // gates_x pipeline
    ull gxr, gxn = 0ull;
    {
        const float* gpx = g_gx + ((size_t)(TS - 1) * 64 + gb0 + b) * 1024 + colA;
        gxr = pk(__ldg(gpx), __ldg(gpx + 256));
    }

#pragma unroll 1
    for (int s = 0; s < TS; ++s) {
        const int cur = s & 1;
        const int nxt = cur ^ 1;

        if (s + 1 < TS) {
            const float* gpx = g_gx + ((size_t)(TS - 2 - s) * 64 + gb0 + b) * 1024 + colA;
            gxn = pk(__ldg(gpx), __ldg(gpx + 256));
        }

        // matvec, rank-ordered with per-rank flag gating
        ull v[32];
#pragma unroll
        for (int i = 0; i < 8; ++i) {
            const int rr = ((int)r + i) & 7;
            if (i) fwait(fl_loc + (unsigned)rr * 4u, (unsigned)s);
            float4 h4 = *(const float4*)&hbuf[cur][rr * 32 + lane][0];
            ull hd0 = dup2(h4.x), hd1 = dup2(h4.y), hd2 = dup2(h4.z), hd3 = dup2(h4.w);
            if (i == 0) {
#pragma unroll
                for (int cpi = 0; cpi < 8; ++cpi) {
                    v[cpi * 4 + 0] = mul2(hd0, wreg[0][cpi]);
                    v[cpi * 4 + 1] = mul2(hd1, wreg[0][cpi]);
                    v[cpi * 4 + 2] = mul2(hd2, wreg[0][cpi]);
                    v[cpi * 4 + 3] = mul2(hd3, wreg[0][cpi]);
                }
            } else {
#pragma unroll
                for (int cpi = 0; cpi < 8; ++cpi) {
                    v[cpi * 4 + 0] = fma2(hd0, wreg[i][cpi], v[cpi * 4 + 0]);
                    v[cpi * 4 + 1] = fma2(hd1, wreg[i][cpi], v[cpi * 4 + 1]);
                    v[cpi * 4 + 2] = fma2(hd2, wreg[i][cpi], v[cpi * 4 + 2]);
                    v[cpi * 4 + 3] = fma2(hd3, wreg[i][cpi], v[cpi * 4 + 3]);
                }
            }
        }

        // reduce-scatter butterfly: lane l ends holding (cp=l>>2, b=l&3)
#pragma unroll
        for (int t = 0; t < 5; ++t) {
            const int mybit = (lane >> t) & 1;
            const int n = 32 >> t;
#pragma unroll
            for (int i = 0; i < 16; ++i) {
                if (i < (n >> 1)) {
                    ull lo = v[2 * i], hi = v[2 * i + 1];
                    ull send = mybit ? lo : hi;
                    ull recv = __shfl_xor_sync(0xffffffffu, send, 1 << t);
                    v[i] = add2(mybit ? hi : lo, recv);
                }
            }
        }

        // epilogue
        {
            float p0, p1;
            upk(add2(v[0], gxr), p0, p1);
            float a0 = sigf(p0);
            float a1 = gp ? tanhap(p1) : sigf(p1);
            ull other = __shfl_xor_sync(0xffffffffu, pk(a0, a1), 4);
            if (gp == 0) {
                float so, tg; upk(other, so, tg);
                cst = a0 * cst + a1 * tg;
                float h1 = so * tanhap(cst);

                yout[((size_t)s * 64 + gb0 + b) * 256 + jj] = h1;
                if (s == TS - 1) {
                    size_t hi_ = (size_t)(gb0 + b) * 256 + jj;
                    hn[hi_] = h1; cn[hi_] = cst;
                } else {
                    const unsigned hoff = hoff_b0 + (unsigned)nxt * 4096u;
#pragma unroll
                    for (int d = 0; d < 8; ++d) {
                        unsigned ra;
                        asm("mapa.shared::cluster.u32 %0, %1, %2;"
                            : "=r"(ra) : "r"(hoff), "r"(d));
                        asm volatile("st.shared::cluster.f32 [%0], %1;"
                                     :: "r"(ra), "f"(h1) : "memory");
                    }
                }
            }
        }
        gxr = gxn;

        __syncthreads();
        if (s < TS - 1 && tid < 8)
            asm volatile("st.release.cluster.shared::cluster.u32 [%0], %1;"
                         :: "r"(fpub), "r"((unsigned)(s + 1)) : "memory");
    }

    asm volatile("barrier.cluster.arrive.aligned;" ::: "memory");
    asm volatile("barrier.cluster.wait.aligned;" ::: "memory");
}

extern "C" void kernel_launch(void* const* d_in, const int* in_sizes, int n_in,
                              void* d_out, int out_size)
{
    const float* x    = (const float*)d_in[0];
    const float* wih0 = (const float*)d_in[1];
    const float* whh0 = (const float*)d_in[2];
    const float* b0   = (const float*)d_in[3];
    const float* wih1 = (const float*)d_in[4];
    const float* whh1 = (const float*)d_in[5];
    const float* b1   = (const float*)d_in[6];
    float* out = (float*)d_out;

    dim3 gg(8, 1024);
    gemm_k<<<gg, 256>>>(x, wih0, b0, 128, 0);
    recur_k<<<128, 256>>>(whh0, out, 0);
    gemm_k<<<gg, 256>>>(x, wih1, b1, 256, 1);
    recur_k<<<128, 256>>>(whh1, out, 1);
}

// round 8
// speedup vs baseline: 1.0027x; 1.0027x over previous
#include <cuda_runtime.h>
#include <cstdint>
#include <cstddef>

typedef unsigned long long ull;

#define TS 2048
#define Y1_ELEMS ((size_t)TS * 64 * 256)

// scratch (allocation-free rule)
__device__ float g_gx[(size_t)TS * 64 * 1024];
__device__ float g_y0[(size_t)TS * 64 * 256];

__device__ __forceinline__ ull fma2(ull a, ull b, ull c) {
    ull d; asm("fma.rn.f32x2 %0,%1,%2,%3;" : "=l"(d) : "l"(a), "l"(b), "l"(c)); return d;
}
__device__ __forceinline__ ull mul2(ull a, ull b) {
    ull d; asm("mul.rn.f32x2 %0,%1,%2;" : "=l"(d) : "l"(a), "l"(b)); return d;
}
__device__ __forceinline__ ull add2(ull a, ull b) {
    ull d; asm("add.rn.f32x2 %0,%1,%2;" : "=l"(d) : "l"(a), "l"(b)); return d;
}
__device__ __forceinline__ ull pk(float lo, float hi) {
    ull r; asm("mov.b64 %0,{%1,%2};" : "=l"(r) : "f"(lo), "f"(hi)); return r;
}
__device__ __forceinline__ void upk(ull a, float& x, float& y) {
    asm("mov.b64 {%0,%1},%2;" : "=f"(x), "=f"(y) : "l"(a));
}
__device__ __forceinline__ ull dup2(float x) {
    ull r; asm("mov.b64 %0,{%1,%1};" : "=l"(r) : "f"(x)); return r;
}
__device__ __forceinline__ float ex2f(float x) {
    float r; asm("ex2.approx.f32 %0,%1;" : "=f"(r) : "f"(x)); return r;
}
__device__ __forceinline__ float rcpf(float x) {
    float r; asm("rcp.approx.f32 %0,%1;" : "=f"(r) : "f"(x)); return r;
}
__device__ __forceinline__ float sigf(float x) {
    return rcpf(1.f + ex2f(-1.44269504f * x));
}
__device__ __forceinline__ float tanhap(float x) {
    float r; asm("tanh.approx.f32 %0,%1;" : "=f"(r) : "f"(x)); return r;
}

__device__ __forceinline__ void mwait(unsigned addr, int phase) {
    asm volatile(
        "{\n\t.reg .pred P;\n"
        "W%=:\n\t"
        "mbarrier.try_wait.parity.acquire.cluster.shared::cta.b64 P, [%0], %1;\n\t"
        "@!P bra W%=;\n\t}"
        :: "r"(addr), "r"((unsigned)phase) : "memory");
}

// ---------------------------------------------------------------------------
// GEMM: g_gx[m][n] = A_row(m) . W[:,n] + bias[n],  M = TS*64, N = 1024
// mode 0: A_row(m) = x + ((m&63)*TS + (m>>6))*128, K=128
// mode 1: A_row(m) = g_y0 + m*256,                 K=256
// ---------------------------------------------------------------------------
__global__ void __launch_bounds__(256, 1)
gemm_k(const float* __restrict__ A, const float* __restrict__ W,
       const float* __restrict__ bias, int K, int mode)
{
    __shared__ float As[16][132];
    __shared__ float Bs[16][128];

    const int tid = threadIdx.x;
    const int n0 = blockIdx.x * 128;
    const int m0 = blockIdx.y * 128;

    const int ar = tid >> 1;
    const int ac = (tid & 1) * 8;
    const int m = m0 + ar;
    const float* arow = mode ? (g_y0 + (size_t)m * 256)
                             : (A + ((size_t)(m & 63) * TS + (m >> 6)) * 128);
    const float* wp = W + (size_t)(tid >> 4) * 1024 + n0 + (tid & 15) * 8;

    const int tm = tid >> 4, tn = tid & 15;

    ull acc[8][4];
#pragma unroll
    for (int i = 0; i < 8; ++i)
#pragma unroll
        for (int j = 0; j < 4; ++j) acc[i][j] = 0ull;

#pragma unroll 1
    for (int k0 = 0; k0 < K; k0 += 16) {
        float4 a0 = *(const float4*)(arow + k0 + ac);
        float4 a1 = *(const float4*)(arow + k0 + ac + 4);
        float4 w0 = *(const float4*)(wp + (size_t)k0 * 1024);
        float4 w1 = *(const float4*)(wp + (size_t)k0 * 1024 + 4);
        __syncthreads();
        As[ac + 0][ar] = a0.x; As[ac + 1][ar] = a0.y;
        As[ac + 2][ar] = a0.z; As[ac + 3][ar] = a0.w;
        As[ac + 4][ar] = a1.x; As[ac + 5][ar] = a1.y;
        As[ac + 6][ar] = a1.z; As[ac + 7][ar] = a1.w;
        *(float4*)&Bs[tid >> 4][(tid & 15) * 8] = w0;
        *(float4*)&Bs[tid >> 4][(tid & 15) * 8 + 4] = w1;
        __syncthreads();
#pragma unroll
        for (int kk = 0; kk < 16; ++kk) {
            float4 av0 = *(const float4*)&As[kk][tm * 8];
            float4 av1 = *(const float4*)&As[kk][tm * 8 + 4];
            float av[8] = {av0.x, av0.y, av0.z, av0.w, av1.x, av1.y, av1.z, av1.w};
            const ull* bp = (const ull*)&Bs[kk][0];
            ull bv[4];
#pragma unroll
            for (int c = 0; c < 4; ++c) bv[c] = bp[tn * 4 + c];
#pragma unroll
            for (int r = 0; r < 8; ++r) {
                ull a2 = dup2(av[r]);
#pragma unroll
                for (int c = 0; c < 4; ++c) acc[r][c] = fma2(a2, bv[c], acc[r][c]);
            }
        }
    }

    float bb[8];
#pragma unroll
    for (int c = 0; c < 8; ++c) bb[c] = bias[n0 + tn * 8 + c];

#pragma unroll
    for (int r = 0; r < 8; ++r) {
        float v[8];
#pragma unroll
        for (int c = 0; c < 4; ++c) upk(acc[r][c], v[2 * c], v[2 * c + 1]);
#pragma unroll
        for (int c = 0; c < 8; ++c) v[c] += bb[c];
        float* op = g_gx + (size_t)(m0 + tm * 8 + r) * 1024 + n0 + tn * 8;
        *(float4*)op = make_float4(v[0], v[1], v[2], v[3]);
        *(float4*)(op + 4) = make_float4(v[4], v[5], v[6], v[7]);
    }
}

// ---------------------------------------------------------------------------
// Recurrence: 16 working clusters x 8 CTAs (grid padded to 152 CTAs; clusters
// >=16 exit). 4 batch elems per cluster. CTA rank r owns hidden units
// [r*32, r*32+32), all gates/batches/k — each warp self-contained for its
// 4 units. Lane l owns k = {i*32 + l}, i = 0..7.
// h exchange per step: producers write a 32x4 local staging tile; after one
// bar.sync, warp w pushes the whole 512B block to cluster rank w with a
// single st.async.v4 per lane (1 DSMEM wavefront per warp, 8 per CTA),
// completing the destination's tx-mbarrier (expect_tx = 8*512 = 4096 B).
// Consumers do one try_wait.parity.acquire per step. Double-buffered h +
// staging make the 2-deep pipeline race-free.
// ---------------------------------------------------------------------------
__global__ void __launch_bounds__(256, 1) __cluster_dims__(8, 1, 1)
recur_k(const float* __restrict__ whh, float* __restrict__ out, int layer)
{
    __shared__ __align__(16) float hbuf[2][256][4];   // [buf][k][batch]
    __shared__ __align__(16) float stg[2][32][4];     // [buf][unit_local][batch]
    __shared__ __align__(16) ull mbar[2];

    const int tid  = threadIdx.x;
    const int w    = tid >> 5;
    const int lane = tid & 31;
    const int cid  = blockIdx.x >> 3;
    if (cid >= 16) return;                  // padding clusters exit whole
    unsigned r;
    asm("mov.u32 %0, %%cluster_ctarank;" : "=r"(r));
    const int gb0 = cid * 4;

    // epilogue identity
    const int cp = lane >> 2;          // col-pair 0..7
    const int b  = lane & 3;           // batch 0..3
    const int gp = cp & 1;             // 0 -> (f,i), 1 -> (o,g)
    const int u  = cp >> 1;            // unit-local in warp 0..3
    const int jj = (int)r * 32 + w * 4 + u;
    const int colA = (2 * gp) * 256 + jj;

    // weights: wreg[i][cp] for k = i*32 + lane, cols (cA, cA+256)
    ull wreg[8][8];
#pragma unroll
    for (int i = 0; i < 8; ++i) {
        const int k = i * 32 + lane;
#pragma unroll
        for (int cpi = 0; cpi < 8; ++cpi) {
            const int cA = (2 * (cpi & 1)) * 256 + (int)r * 32 + w * 4 + (cpi >> 1);
            const float* wp = whh + (size_t)k * 1024 + cA;
            wreg[i][cpi] = pk(wp[0], wp[256]);
        }
    }

    unsigned hb_loc  = (unsigned)__cvta_generic_to_shared(&hbuf[0][0][0]);
    unsigned bar_loc = (unsigned)__cvta_generic_to_shared(&mbar[0]);
    // warp w pushes to cluster rank w
    unsigned dst_data, dst_bar;
    asm("mapa.shared::cluster.u32 %0, %1, %2;" : "=r"(dst_data) : "r"(hb_loc), "r"(w));
    asm("mapa.shared::cluster.u32 %0, %1, %2;" : "=r"(dst_bar)  : "r"(bar_loc), "r"(w));

    if (tid == 0) {
        asm volatile("mbarrier.init.shared.b64 [%0], %1;" :: "r"(bar_loc), "r"(1u) : "memory");
        asm volatile("mbarrier.init.shared.b64 [%0], %1;" :: "r"(bar_loc + 8), "r"(1u) : "memory");
        asm volatile("fence.mbarrier_init.release.cluster;" ::: "memory");
    }
    for (int i = tid; i < 2 * 256 * 4; i += 256)
        ((float*)hbuf)[i] = 0.f;
    __syncthreads();
    asm volatile("barrier.cluster.arrive.aligned;" ::: "memory");
    asm volatile("barrier.cluster.wait.aligned;" ::: "memory");

    float cst = 0.f;
    float* yout = layer ? out : g_y0;
    float* hn = out + Y1_ELEMS + (size_t)layer * 16384;
    float* cn = out + Y1_ELEMS + 32768 + (size_t)layer * 16384;

    // gates_x pipeline
    ull gxr, gxn = 0ull;
    {
        const float* gpx = g_gx + ((size_t)(TS - 1) * 64 + gb0 + b) * 1024 + colA;
        gxr = pk(__ldg(gpx), __ldg(gpx + 256));
    }

    int par0 = 0, par1 = 0;

#pragma unroll 1
    for (int s = 0; s < TS; ++s) {
        const int cur = s & 1;
        const int nxt = cur ^ 1;

        if (s + 1 < TS) {
            const float* gpx = g_gx + ((size_t)(TS - 2 - s) * 64 + gb0 + b) * 1024 + colA;
            gxn = pk(__ldg(gpx), __ldg(gpx + 256));
            // arm next buffer's tx barrier (arrive count 1 + 4096 bytes)
            if (tid == 0)
                asm volatile("mbarrier.arrive.expect_tx.shared.b64 _, [%0], %1;"
                             :: "r"(bar_loc + (unsigned)nxt * 8u), "r"(4096u) : "memory");
        }

        // wait for this step's h (step 0 reads the zero-initialized buffer)
        if (s) {
            if (cur == 0) { mwait(bar_loc, par0);      par0 ^= 1; }
            else          { mwait(bar_loc + 8, par1);  par1 ^= 1; }
        }

        // matvec: v[cp*4 + bb], k split over i (8 blocks of 32, lane-coalesced)
        ull v[32];
#pragma unroll
        for (int i = 0; i < 8; ++i) {
            float4 h4 = *(const float4*)&hbuf[cur][i * 32 + lane][0];
            ull hd0 = dup2(h4.x), hd1 = dup2(h4.y), hd2 = dup2(h4.z), hd3 = dup2(h4.w);
            if (i == 0) {
#pragma unroll
                for (int cpi = 0; cpi < 8; ++cpi) {
                    v[cpi * 4 + 0] = mul2(hd0, wreg[0][cpi]);
                    v[cpi * 4 + 1] = mul2(hd1, wreg[0][cpi]);
                    v[cpi * 4 + 2] = mul2(hd2, wreg[0][cpi]);
                    v[cpi * 4 + 3] = mul2(hd3, wreg[0][cpi]);
                }
            } else {
#pragma unroll
                for (int cpi = 0; cpi < 8; ++cpi) {
                    v[cpi * 4 + 0] = fma2(hd0, wreg[i][cpi], v[cpi * 4 + 0]);
                    v[cpi * 4 + 1] = fma2(hd1, wreg[i][cpi], v[cpi * 4 + 1]);
                    v[cpi * 4 + 2] = fma2(hd2, wreg[i][cpi], v[cpi * 4 + 2]);
                    v[cpi * 4 + 3] = fma2(hd3, wreg[i][cpi], v[cpi * 4 + 3]);
                }
            }
        }

        // reduce-scatter butterfly: lane l ends holding (cp=l>>2, b=l&3)
#pragma unroll
        for (int t = 0; t < 5; ++t) {
            const int mybit = (lane >> t) & 1;
            const int n = 32 >> t;
#pragma unroll
            for (int i = 0; i < 16; ++i) {
                if (i < (n >> 1)) {
                    ull lo = v[2 * i], hi = v[2 * i + 1];
                    ull send = mybit ? lo : hi;
                    ull recv = __shfl_xor_sync(0xffffffffu, send, 1 << t);
                    v[i] = add2(mybit ? hi : lo, recv);
                }
            }
        }

        // epilogue
        {
            float p0, p1;
            upk(add2(v[0], gxr), p0, p1);
            float a0 = sigf(p0);
            float a1 = gp ? tanhap(p1) : sigf(p1);
            ull other = __shfl_xor_sync(0xffffffffu, pk(a0, a1), 4);
            if (gp == 0) {
                float so, tg; upk(other, so, tg);
                cst = a0 * cst + a1 * tg;
                float h1 = so * tanhap(cst);

                yout[((size_t)s * 64 + gb0 + b) * 256 + jj] = h1;
                if (s == TS - 1) {
                    size_t hi_ = (size_t)(gb0 + b) * 256 + jj;
                    hn[hi_] = h1; cn[hi_] = cst;
                } else {
                    stg[cur][w * 4 + u][b] = h1;
                }
            }
        }
        gxr = gxn;

        if (s + 1 < TS) {
            __syncthreads();
            // warp w pushes CTA's 128-float h block to rank w (one v4 per lane)
            float4 hv = *(const float4*)&stg[cur][lane][0];
            unsigned daddr = dst_data + (unsigned)((nxt * 256 + (int)r * 32 + lane) * 16);
            unsigned baddr = dst_bar + (unsigned)nxt * 8u;
            asm volatile(
                "st.async.shared::cluster.mbarrier::complete_tx::bytes.v4.f32 "
                "[%0], {%1,%2,%3,%4}, [%5];"
                :: "r"(daddr), "f"(hv.x), "f"(hv.y), "f"(hv.z), "f"(hv.w), "r"(baddr)
                : "memory");
        }
    }

    asm volatile("barrier.cluster.arrive.aligned;" ::: "memory");
    asm volatile("barrier.cluster.wait.aligned;" ::: "memory");
}

extern "C" void kernel_launch(void* const* d_in, const int* in_sizes, int n_in,
                              void* d_out, int out_size)
{
    const float* x    = (const float*)d_in[0];
    const float* wih0 = (const float*)d_in[1];
    const float* whh0 = (const float*)d_in[2];
    const float* b0   = (const float*)d_in[3];
    const float* wih1 = (const float*)d_in[4];
    const float* whh1 = (const float*)d_in[5];
    const float* b1   = (const float*)d_in[6];
    float* out = (float*)d_out;

    dim3 gg(8, 1024);
    gemm_k<<<gg, 256>>>(x, wih0, b0, 128, 0);
    recur_k<<<152, 256>>>(whh0, out, 0);
    gemm_k<<<gg, 256>>>(x, wih1, b1, 256, 1);
    recur_k<<<152, 256>>>(whh1, out, 1);
}

// round 9
// speedup vs baseline: 1.4269x; 1.4231x over previous
#include <cuda_runtime.h>
#include <cstdint>
#include <cstddef>

typedef unsigned long long ull;

#define TS 2048
#define Y1_ELEMS ((size_t)TS * 64 * 256)

// scratch (allocation-free rule)
__device__ float g_gx[(size_t)TS * 64 * 1024];
__device__ float g_y0[(size_t)TS * 64 * 256];
// h exchange through L2: [buf][group][k][batch]
__device__ float g_hx[2][16][256][4];
// per-layer, per-group monotonic step flags + finish counters (padded lines)
__device__ __align__(128) unsigned g_flag[2][16][32];
__device__ __align__(128) unsigned g_fin[2][16][32];

__device__ __forceinline__ ull fma2(ull a, ull b, ull c) {
    ull d; asm("fma.rn.f32x2 %0,%1,%2,%3;" : "=l"(d) : "l"(a), "l"(b), "l"(c)); return d;
}
__device__ __forceinline__ ull mul2(ull a, ull b) {
    ull d; asm("mul.rn.f32x2 %0,%1,%2;" : "=l"(d) : "l"(a), "l"(b)); return d;
}
__device__ __forceinline__ ull add2(ull a, ull b) {
    ull d; asm("add.rn.f32x2 %0,%1,%2;" : "=l"(d) : "l"(a), "l"(b)); return d;
}
__device__ __forceinline__ ull pk(float lo, float hi) {
    ull r; asm("mov.b64 %0,{%1,%2};" : "=l"(r) : "f"(lo), "f"(hi)); return r;
}
__device__ __forceinline__ void upk(ull a, float& x, float& y) {
    asm("mov.b64 {%0,%1},%2;" : "=f"(x), "=f"(y) : "l"(a));
}
__device__ __forceinline__ ull dup2(float x) {
    ull r; asm("mov.b64 %0,{%1,%1};" : "=l"(r) : "f"(x)); return r;
}
__device__ __forceinline__ float ex2f(float x) {
    float r; asm("ex2.approx.f32 %0,%1;" : "=f"(r) : "f"(x)); return r;
}
__device__ __forceinline__ float rcpf(float x) {
    float r; asm("rcp.approx.f32 %0,%1;" : "=f"(r) : "f"(x)); return r;
}
__device__ __forceinline__ float sigf(float x) {
    return rcpf(1.f + ex2f(-1.44269504f * x));
}
__device__ __forceinline__ float tanhap(float x) {
    float r; asm("tanh.approx.f32 %0,%1;" : "=f"(r) : "f"(x)); return r;
}
__device__ __forceinline__ unsigned ldacq(const unsigned* p) {
    unsigned v;
    asm volatile("ld.acquire.gpu.global.u32 %0,[%1];" : "=r"(v) : "l"(p) : "memory");
    return v;
}

// ---------------------------------------------------------------------------
// GEMM: g_gx[m][n] = A_row(m) . W[:,n] + bias[n],  M = TS*64, N = 1024
// mode 0: A_row(m) = x + ((m&63)*TS + (m>>6))*128, K=128
// mode 1: A_row(m) = g_y0 + m*256,                 K=256
// ---------------------------------------------------------------------------
__global__ void __launch_bounds__(256, 1)
gemm_k(const float* __restrict__ A, const float* __restrict__ W,
       const float* __restrict__ bias, int K, int mode)
{
    __shared__ float As[16][132];
    __shared__ float Bs[16][128];

    const int tid = threadIdx.x;
    const int n0 = blockIdx.x * 128;
    const int m0 = blockIdx.y * 128;

    const int ar = tid >> 1;
    const int ac = (tid & 1) * 8;
    const int m = m0 + ar;
    const float* arow = mode ? (g_y0 + (size_t)m * 256)
                             : (A + ((size_t)(m & 63) * TS + (m >> 6)) * 128);
    const float* wp = W + (size_t)(tid >> 4) * 1024 + n0 + (tid & 15) * 8;

    const int tm = tid >> 4, tn = tid & 15;

    ull acc[8][4];
#pragma unroll
    for (int i = 0; i < 8; ++i)
#pragma unroll
        for (int j = 0; j < 4; ++j) acc[i][j] = 0ull;

#pragma unroll 1
    for (int k0 = 0; k0 < K; k0 += 16) {
        float4 a0 = *(const float4*)(arow + k0 + ac);
        float4 a1 = *(const float4*)(arow + k0 + ac + 4);
        float4 w0 = *(const float4*)(wp + (size_t)k0 * 1024);
        float4 w1 = *(const float4*)(wp + (size_t)k0 * 1024 + 4);
        __syncthreads();
        As[ac + 0][ar] = a0.x; As[ac + 1][ar] = a0.y;
        As[ac + 2][ar] = a0.z; As[ac + 3][ar] = a0.w;
        As[ac + 4][ar] = a1.x; As[ac + 5][ar] = a1.y;
        As[ac + 6][ar] = a1.z; As[ac + 7][ar] = a1.w;
        *(float4*)&Bs[tid >> 4][(tid & 15) * 8] = w0;
        *(float4*)&Bs[tid >> 4][(tid & 15) * 8 + 4] = w1;
        __syncthreads();
#pragma unroll
        for (int kk = 0; kk < 16; ++kk) {
            float4 av0 = *(const float4*)&As[kk][tm * 8];
            float4 av1 = *(const float4*)&As[kk][tm * 8 + 4];
            float av[8] = {av0.x, av0.y, av0.z, av0.w, av1.x, av1.y, av1.z, av1.w};
            const ull* bp = (const ull*)&Bs[kk][0];
            ull bv[4];
#pragma unroll
            for (int c = 0; c < 4; ++c) bv[c] = bp[tn * 4 + c];
#pragma unroll
            for (int r = 0; r < 8; ++r) {
                ull a2 = dup2(av[r]);
#pragma unroll
                for (int c = 0; c < 4; ++c) acc[r][c] = fma2(a2, bv[c], acc[r][c]);
            }
        }
    }

    float bb[8];
#pragma unroll
    for (int c = 0; c < 8; ++c) bb[c] = bias[n0 + tn * 8 + c];

#pragma unroll
    for (int r = 0; r < 8; ++r) {
        float v[8];
#pragma unroll
        for (int c = 0; c < 4; ++c) upk(acc[r][c], v[2 * c], v[2 * c + 1]);
#pragma unroll
        for (int c = 0; c < 8; ++c) v[c] += bb[c];
        float* op = g_gx + (size_t)(m0 + tm * 8 + r) * 1024 + n0 + tn * 8;
        *(float4*)op = make_float4(v[0], v[1], v[2], v[3]);
        *(float4*)(op + 4) = make_float4(v[4], v[5], v[6], v[7]);
    }
}

// ---------------------------------------------------------------------------
// Recurrence: 128 plain CTAs; group g = blockIdx>>3 (8 CTAs), rank = blockIdx&7.
// Group handles batches [g*4, g*4+4). Rank r owns hidden units [r*32, r*32+32).
// Warp w owns 4 units x 4 gates x 4 batches, all k. Lane l: k = {i*32+l}.
// h exchange through L2 (g_hx double buffer) + per-group monotonic flag:
//   publish: STG h -> __syncthreads -> tid0: membar.gl + red.add(flag,1)
//   consume: tid0 spins ld.acquire.gpu flag >= 8*s -> __syncthreads ->
//            matvec reads g_hx via __ldcg (L2-only; no stale L1).
// Flags reset in-kernel (per-group finish counter) => graph-replay safe.
// ---------------------------------------------------------------------------
__global__ void __launch_bounds__(256, 1)
recur_k(const float* __restrict__ whh, float* __restrict__ out, int layer)
{
    const int tid  = threadIdx.x;
    const int w    = tid >> 5;
    const int lane = tid & 31;
    const int grp  = blockIdx.x >> 3;
    const int r    = blockIdx.x & 7;
    const int gb0  = grp * 4;

    // epilogue identity
    const int cp = lane >> 2;          // col-pair 0..7
    const int b  = lane & 3;           // batch 0..3
    const int gp = cp & 1;             // 0 -> (f,i), 1 -> (o,g)
    const int u  = cp >> 1;            // unit-local in warp 0..3
    const int jj = r * 32 + w * 4 + u;
    const int colA = (2 * gp) * 256 + jj;

    // weights: wreg[i][cp] for k = i*32 + lane, cols (cA, cA+256)
    ull wreg[8][8];
#pragma unroll
    for (int i = 0; i < 8; ++i) {
        const int k = i * 32 + lane;
#pragma unroll
        for (int cpi = 0; cpi < 8; ++cpi) {
            const int cA = (2 * (cpi & 1)) * 256 + r * 32 + w * 4 + (cpi >> 1);
            const float* wp = whh + (size_t)k * 1024 + cA;
            wreg[i][cpi] = pk(wp[0], wp[256]);
        }
    }

    unsigned* flag = &g_flag[layer][grp][0];
    unsigned* fin  = &g_fin[layer][grp][0];

    float cst = 0.f;
    float* yout = layer ? out : g_y0;
    float* hn = out + Y1_ELEMS + (size_t)layer * 16384;
    float* cn = out + Y1_ELEMS + 32768 + (size_t)layer * 16384;

    // gates_x pipeline
    ull gxr, gxn = 0ull;
    {
        const float* gpx = g_gx + ((size_t)(TS - 1) * 64 + gb0 + b) * 1024 + colA;
        gxr = pk(__ldg(gpx), __ldg(gpx + 256));
    }

#pragma unroll 1
    for (int s = 0; s < TS; ++s) {
        const int cur = s & 1;
        const int nxt = cur ^ 1;

        if (s + 1 < TS) {
            const float* gpx = g_gx + ((size_t)(TS - 2 - s) * 64 + gb0 + b) * 1024 + colA;
            gxn = pk(__ldg(gpx), __ldg(gpx + 256));
        }

        // wait: all 8 ranks of this group have published step s-1
        if (s) {
            if (tid == 0) {
                const unsigned tgt = 8u * (unsigned)s;
#pragma unroll 1
                while (ldacq(flag) < tgt) { }
            }
            __syncthreads();
        }

        // matvec: v[cp*4 + bb]; h read straight from L2 (step 0: h = 0)
        ull v[32];
#pragma unroll
        for (int i = 0; i < 8; ++i) {
            float4 h4 = make_float4(0.f, 0.f, 0.f, 0.f);
            if (s) h4 = __ldcg((const float4*)&g_hx[cur][grp][i * 32 + lane][0]);
            ull hd0 = dup2(h4.x), hd1 = dup2(h4.y), hd2 = dup2(h4.z), hd3 = dup2(h4.w);
            if (i == 0) {
#pragma unroll
                for (int cpi = 0; cpi < 8; ++cpi) {
                    v[cpi * 4 + 0] = mul2(hd0, wreg[0][cpi]);
                    v[cpi * 4 + 1] = mul2(hd1, wreg[0][cpi]);
                    v[cpi * 4 + 2] = mul2(hd2, wreg[0][cpi]);
                    v[cpi * 4 + 3] = mul2(hd3, wreg[0][cpi]);
                }
            } else {
#pragma unroll
                for (int cpi = 0; cpi < 8; ++cpi) {
                    v[cpi * 4 + 0] = fma2(hd0, wreg[i][cpi], v[cpi * 4 + 0]);
                    v[cpi * 4 + 1] = fma2(hd1, wreg[i][cpi], v[cpi * 4 + 1]);
                    v[cpi * 4 + 2] = fma2(hd2, wreg[i][cpi], v[cpi * 4 + 2]);
                    v[cpi * 4 + 3] = fma2(hd3, wreg[i][cpi], v[cpi * 4 + 3]);
                }
            }
        }

        // reduce-scatter butterfly: lane l ends holding (cp=l>>2, b=l&3)
#pragma unroll
        for (int t = 0; t < 5; ++t) {
            const int mybit = (lane >> t) & 1;
            const int n = 32 >> t;
#pragma unroll
            for (int i = 0; i < 16; ++i) {
                if (i < (n >> 1)) {
                    ull lo = v[2 * i], hi = v[2 * i + 1];
                    ull send = mybit ? lo : hi;
                    ull recv = __shfl_xor_sync(0xffffffffu, send, 1 << t);
                    v[i] = add2(mybit ? hi : lo, recv);
                }
            }
        }

        // epilogue
        {
            float p0, p1;
            upk(add2(v[0], gxr), p0, p1);
            float a0 = sigf(p0);
            float a1 = gp ? tanhap(p1) : sigf(p1);
            ull other = __shfl_xor_sync(0xffffffffu, pk(a0, a1), 4);
            if (gp == 0) {
                float so, tg; upk(other, so, tg);
                cst = a0 * cst + a1 * tg;
                float h1 = so * tanhap(cst);

                yout[((size_t)s * 64 + gb0 + b) * 256 + jj] = h1;
                if (s == TS - 1) {
                    size_t hi_ = (size_t)(gb0 + b) * 256 + jj;
                    hn[hi_] = h1; cn[hi_] = cst;
                } else {
                    g_hx[nxt][grp][jj][b] = h1;
                }
            }
        }
        gxr = gxn;

        __syncthreads();
        if (s < TS - 1 && tid == 0) {
            asm volatile("membar.gl;" ::: "memory");
            asm volatile("red.global.add.u32 [%0], 1;" :: "l"(flag) : "memory");
        }
    }

    // reset flags for the next graph replay (deterministic launches)
    __syncthreads();
    if (tid == 0) {
        asm volatile("membar.gl;" ::: "memory");
        asm volatile("red.global.add.u32 [%0], 1;" :: "l"(fin) : "memory");
        if (r == 0) {
#pragma unroll 1
            while (ldacq(fin) < 8u) { }
            asm volatile("st.global.u32 [%0], %1;" :: "l"(flag), "r"(0u) : "memory");
            asm volatile("st.global.u32 [%0], %1;" :: "l"(fin), "r"(0u) : "memory");
        }
    }
}

extern "C" void kernel_launch(void* const* d_in, const int* in_sizes, int n_in,
                              void* d_out, int out_size)
{
    const float* x    = (const float*)d_in[0];
    const float* wih0 = (const float*)d_in[1];
    const float* whh0 = (const float*)d_in[2];
    const float* b0   = (const float*)d_in[3];
    const float* wih1 = (const float*)d_in[4];
    const float* whh1 = (const float*)d_in[5];
    const float* b1   = (const float*)d_in[6];
    float* out = (float*)d_out;

    dim3 gg(8, 1024);
    gemm_k<<<gg, 256>>>(x, wih0, b0, 128, 0);
    recur_k<<<128, 256>>>(whh0, out, 0);
    gemm_k<<<gg, 256>>>(x, wih1, b1, 256, 1);
    recur_k<<<128, 256>>>(whh1, out, 1);
}

// round 10
// speedup vs baseline: 1.4546x; 1.0194x over previous
#include <cuda_runtime.h>
#include <cstdint>
#include <cstddef>

typedef unsigned long long ull;

#define TS 2048
#define Y1_ELEMS ((size_t)TS * 64 * 256)

// scratch (allocation-free rule)
__device__ float g_gx[(size_t)TS * 64 * 1024];
__device__ float g_y0[(size_t)TS * 64 * 256];
// h exchange through L2: [buf][group][k][batch]
__device__ float g_hx[2][16][256][4];
// per-layer, per-group, PER-RANK monotonic flags (each on own 128B line)
__device__ __align__(128) unsigned g_flag[2][16][8][32];
__device__ __align__(128) unsigned g_fin[2][16][32];

__device__ __forceinline__ ull fma2(ull a, ull b, ull c) {
    ull d; asm("fma.rn.f32x2 %0,%1,%2,%3;" : "=l"(d) : "l"(a), "l"(b), "l"(c)); return d;
}
__device__ __forceinline__ ull mul2(ull a, ull b) {
    ull d; asm("mul.rn.f32x2 %0,%1,%2;" : "=l"(d) : "l"(a), "l"(b)); return d;
}
__device__ __forceinline__ ull add2(ull a, ull b) {
    ull d; asm("add.rn.f32x2 %0,%1,%2;" : "=l"(d) : "l"(a), "l"(b)); return d;
}
__device__ __forceinline__ ull pk(float lo, float hi) {
    ull r; asm("mov.b64 %0,{%1,%2};" : "=l"(r) : "f"(lo), "f"(hi)); return r;
}
__device__ __forceinline__ void upk(ull a, float& x, float& y) {
    asm("mov.b64 {%0,%1},%2;" : "=f"(x), "=f"(y) : "l"(a));
}
__device__ __forceinline__ ull dup2(float x) {
    ull r; asm("mov.b64 %0,{%1,%1};" : "=l"(r) : "f"(x)); return r;
}
__device__ __forceinline__ float ex2f(float x) {
    float r; asm("ex2.approx.f32 %0,%1;" : "=f"(r) : "f"(x)); return r;
}
__device__ __forceinline__ float rcpf(float x) {
    float r; asm("rcp.approx.f32 %0,%1;" : "=f"(r) : "f"(x)); return r;
}
__device__ __forceinline__ float sigf(float x) {
    return rcpf(1.f + ex2f(-1.44269504f * x));
}
__device__ __forceinline__ float tanhap(float x) {
    float r; asm("tanh.approx.f32 %0,%1;" : "=f"(r) : "f"(x)); return r;
}
__device__ __forceinline__ unsigned ldacq(const unsigned* p) {
    unsigned v;
    asm volatile("ld.acquire.gpu.global.u32 %0,[%1];" : "=r"(v) : "l"(p) : "memory");
    return v;
}

// ---------------------------------------------------------------------------
// GEMM: g_gx[m][n] = A_row(m) . W[:,n] + bias[n],  M = TS*64, N = 1024
// mode 0: A_row(m) = x + ((m&63)*TS + (m>>6))*128, K=128
// mode 1: A_row(m) = g_y0 + m*256,                 K=256
// ---------------------------------------------------------------------------
__global__ void __launch_bounds__(256, 1)
gemm_k(const float* __restrict__ A, const float* __restrict__ W,
       const float* __restrict__ bias, int K, int mode)
{
    __shared__ float As[16][132];
    __shared__ float Bs[16][128];

    const int tid = threadIdx.x;
    const int n0 = blockIdx.x * 128;
    const int m0 = blockIdx.y * 128;

    const int ar = tid >> 1;
    const int ac = (tid & 1) * 8;
    const int m = m0 + ar;
    const float* arow = mode ? (g_y0 + (size_t)m * 256)
                             : (A + ((size_t)(m & 63) * TS + (m >> 6)) * 128);
    const float* wp = W + (size_t)(tid >> 4) * 1024 + n0 + (tid & 15) * 8;

    const int tm = tid >> 4, tn = tid & 15;

    ull acc[8][4];
#pragma unroll
    for (int i = 0; i < 8; ++i)
#pragma unroll
        for (int j = 0; j < 4; ++j) acc[i][j] = 0ull;

#pragma unroll 1
    for (int k0 = 0; k0 < K; k0 += 16) {
        float4 a0 = *(const float4*)(arow + k0 + ac);
        float4 a1 = *(const float4*)(arow + k0 + ac + 4);
        float4 w0 = *(const float4*)(wp + (size_t)k0 * 1024);
        float4 w1 = *(const float4*)(wp + (size_t)k0 * 1024 + 4);
        __syncthreads();
        As[ac + 0][ar] = a0.x; As[ac + 1][ar] = a0.y;
        As[ac + 2][ar] = a0.z; As[ac + 3][ar] = a0.w;
        As[ac + 4][ar] = a1.x; As[ac + 5][ar] = a1.y;
        As[ac + 6][ar] = a1.z; As[ac + 7][ar] = a1.w;
        *(float4*)&Bs[tid >> 4][(tid & 15) * 8] = w0;
        *(float4*)&Bs[tid >> 4][(tid & 15) * 8 + 4] = w1;
        __syncthreads();
#pragma unroll
        for (int kk = 0; kk < 16; ++kk) {
            float4 av0 = *(const float4*)&As[kk][tm * 8];
            float4 av1 = *(const float4*)&As[kk][tm * 8 + 4];
            float av[8] = {av0.x, av0.y, av0.z, av0.w, av1.x, av1.y, av1.z, av1.w};
            const ull* bp = (const ull*)&Bs[kk][0];
            ull bv[4];
#pragma unroll
            for (int c = 0; c < 4; ++c) bv[c] = bp[tn * 4 + c];
#pragma unroll
            for (int r = 0; r < 8; ++r) {
                ull a2 = dup2(av[r]);
#pragma unroll
                for (int c = 0; c < 4; ++c) acc[r][c] = fma2(a2, bv[c], acc[r][c]);
            }
        }
    }

    float bb[8];
#pragma unroll
    for (int c = 0; c < 8; ++c) bb[c] = bias[n0 + tn * 8 + c];

#pragma unroll
    for (int r = 0; r < 8; ++r) {
        float v[8];
#pragma unroll
        for (int c = 0; c < 4; ++c) upk(acc[r][c], v[2 * c], v[2 * c + 1]);
#pragma unroll
        for (int c = 0; c < 8; ++c) v[c] += bb[c];
        float* op = g_gx + (size_t)(m0 + tm * 8 + r) * 1024 + n0 + tn * 8;
        *(float4*)op = make_float4(v[0], v[1], v[2], v[3]);
        *(float4*)(op + 4) = make_float4(v[4], v[5], v[6], v[7]);
    }
}

// ---------------------------------------------------------------------------
// Recurrence: 128 plain CTAs; group g = blockIdx>>3 (8 CTAs), rank = blockIdx&7.
// Group handles batches [g*4, g*4+4). Rank r owns hidden units [r*32, r*32+32).
// Warp w owns 4 units x 4 gates x 4 batches, all k. Lane l: k = {i*32+l}.
// h exchange through L2 (g_hx double buffer). Publish path (the critical
// serial chain) is the minimal release/acquire message-passing pattern:
//   STG h -> bar.sync -> tid0 st.release.gpu flag[r]=s+1      (producer)
//   tids 0..7 spin ld.acquire.gpu flag[rr]>=s -> bar.sync -> ldcg h (consumer)
// yout / hn / cn stores issue AFTER the publish (off the chain).
// Per-rank flag lines kill the same-address atomic serialization of R9.
// ---------------------------------------------------------------------------
__global__ void __launch_bounds__(256, 1)
recur_k(const float* __restrict__ whh, float* __restrict__ out, int layer)
{
    const int tid  = threadIdx.x;
    const int w    = tid >> 5;
    const int lane = tid & 31;
    const int grp  = blockIdx.x >> 3;
    const int r    = blockIdx.x & 7;
    const int gb0  = grp * 4;

    // epilogue identity
    const int cp = lane >> 2;          // col-pair 0..7
    const int b  = lane & 3;           // batch 0..3
    const int gp = cp & 1;             // 0 -> (f,i), 1 -> (o,g)
    const int u  = cp >> 1;            // unit-local in warp 0..3
    const int jj = r * 32 + w * 4 + u;
    const int colA = (2 * gp) * 256 + jj;

    // weights: wreg[i][cp] for k = i*32 + lane, cols (cA, cA+256)
    ull wreg[8][8];
#pragma unroll
    for (int i = 0; i < 8; ++i) {
        const int k = i * 32 + lane;
#pragma unroll
        for (int cpi = 0; cpi < 8; ++cpi) {
            const int cA = (2 * (cpi & 1)) * 256 + r * 32 + w * 4 + (cpi >> 1);
            const float* wp = whh + (size_t)k * 1024 + cA;
            wreg[i][cpi] = pk(wp[0], wp[256]);
        }
    }

    unsigned* myflag = &g_flag[layer][grp][r][0];
    unsigned* fin    = &g_fin[layer][grp][0];

    float cst = 0.f;
    float* yout = layer ? out : g_y0;
    float* hn = out + Y1_ELEMS + (size_t)layer * 16384;
    float* cn = out + Y1_ELEMS + 32768 + (size_t)layer * 16384;

    // gates_x pipeline
    ull gxr, gxn = 0ull;
    {
        const float* gpx = g_gx + ((size_t)(TS - 1) * 64 + gb0 + b) * 1024 + colA;
        gxr = pk(__ldg(gpx), __ldg(gpx + 256));
    }

#pragma unroll 1
    for (int s = 0; s < TS; ++s) {
        const int cur = s & 1;
        const int nxt = cur ^ 1;

        if (s + 1 < TS) {
            const float* gpx = g_gx + ((size_t)(TS - 2 - s) * 64 + gb0 + b) * 1024 + colA;
            gxn = pk(__ldg(gpx), __ldg(gpx + 256));
        }

        // wait: each of tids 0..7 watches one rank's flag (parallel discovery)
        if (s) {
            if (tid < 8) {
                const unsigned tgt = (unsigned)s;
                const unsigned* fp = &g_flag[layer][grp][tid][0];
#pragma unroll 1
                while (ldacq(fp) < tgt) { }
            }
            __syncthreads();
        }

        // matvec: v[cp*4 + bb]; h read straight from L2 (step 0: h = 0)
        ull v[32];
#pragma unroll
        for (int i = 0; i < 8; ++i) {
            float4 h4 = make_float4(0.f, 0.f, 0.f, 0.f);
            if (s) h4 = __ldcg((const float4*)&g_hx[cur][grp][i * 32 + lane][0]);
            ull hd0 = dup2(h4.x), hd1 = dup2(h4.y), hd2 = dup2(h4.z), hd3 = dup2(h4.w);
            if (i == 0) {
#pragma unroll
                for (int cpi = 0; cpi < 8; ++cpi) {
                    v[cpi * 4 + 0] = mul2(hd0, wreg[0][cpi]);
                    v[cpi * 4 + 1] = mul2(hd1, wreg[0][cpi]);
                    v[cpi * 4 + 2] = mul2(hd2, wreg[0][cpi]);
                    v[cpi * 4 + 3] = mul2(hd3, wreg[0][cpi]);
                }
            } else {
#pragma unroll
                for (int cpi = 0; cpi < 8; ++cpi) {
                    v[cpi * 4 + 0] = fma2(hd0, wreg[i][cpi], v[cpi * 4 + 0]);
                    v[cpi * 4 + 1] = fma2(hd1, wreg[i][cpi], v[cpi * 4 + 1]);
                    v[cpi * 4 + 2] = fma2(hd2, wreg[i][cpi], v[cpi * 4 + 2]);
                    v[cpi * 4 + 3] = fma2(hd3, wreg[i][cpi], v[cpi * 4 + 3]);
                }
            }
        }

        // reduce-scatter butterfly: lane l ends holding (cp=l>>2, b=l&3)
#pragma unroll
        for (int t = 0; t < 5; ++t) {
            const int mybit = (lane >> t) & 1;
            const int n = 32 >> t;
#pragma unroll
            for (int i = 0; i < 16; ++i) {
                if (i < (n >> 1)) {
                    ull lo = v[2 * i], hi = v[2 * i + 1];
                    ull send = mybit ? lo : hi;
                    ull recv = __shfl_xor_sync(0xffffffffu, send, 1 << t);
                    v[i] = add2(mybit ? hi : lo, recv);
                }
            }
        }

        // epilogue: compute h, store ONLY g_hx before the publish
        float h1 = 0.f;
        {
            float p0, p1;
            upk(add2(v[0], gxr), p0, p1);
            float a0 = sigf(p0);
            float a1 = gp ? tanhap(p1) : sigf(p1);
            ull other = __shfl_xor_sync(0xffffffffu, pk(a0, a1), 4);
            if (gp == 0) {
                float so, tg; upk(other, so, tg);
                cst = a0 * cst + a1 * tg;
                h1 = so * tanhap(cst);
                if (s < TS - 1)
                    g_hx[nxt][grp][jj][b] = h1;
            }
        }
        gxr = gxn;

        __syncthreads();              // h stores happen-before the release
        if (s < TS - 1 && tid == 0)
            asm volatile("st.release.gpu.global.u32 [%0], %1;"
                         :: "l"(myflag), "r"((unsigned)(s + 1)) : "memory");

        // outputs AFTER the publish — off the critical chain
        if (gp == 0) {
            yout[((size_t)s * 64 + gb0 + b) * 256 + jj] = h1;
            if (s == TS - 1) {
                size_t hi_ = (size_t)(gb0 + b) * 256 + jj;
                hn[hi_] = h1; cn[hi_] = cst;
            }
        }
    }

    // reset flags for the next graph replay (deterministic launches)
    __syncthreads();
    if (tid == 0) {
        asm volatile("red.release.gpu.global.add.u32 [%0], 1;" :: "l"(fin) : "memory");
        if (r == 0) {
#pragma unroll 1
            while (ldacq(fin) < 8u) { }
#pragma unroll
            for (int d = 0; d < 8; ++d)
                asm volatile("st.global.u32 [%0], %1;"
                             :: "l"(&g_flag[layer][grp][d][0]), "r"(0u) : "memory");
            asm volatile("st.global.u32 [%0], %1;" :: "l"(fin), "r"(0u) : "memory");
        }
    }
}

extern "C" void kernel_launch(void* const* d_in, const int* in_sizes, int n_in,
                              void* d_out, int out_size)
{
    const float* x    = (const float*)d_in[0];
    const float* wih0 = (const float*)d_in[1];
    const float* whh0 = (const float*)d_in[2];
    const float* b0   = (const float*)d_in[3];
    const float* wih1 = (const float*)d_in[4];
    const float* whh1 = (const float*)d_in[5];
    const float* b1   = (const float*)d_in[6];
    float* out = (float*)d_out;

    dim3 gg(8, 1024);
    gemm_k<<<gg, 256>>>(x, wih0, b0, 128, 0);
    recur_k<<<128, 256>>>(whh0, out, 0);
    gemm_k<<<gg, 256>>>(x, wih1, b1, 256, 1);
    recur_k<<<128, 256>>>(whh1, out, 1);
}